// round 10
// baseline (speedup 1.0000x reference)
#include <cuda_runtime.h>
#include <cuda_fp16.h>
#include <cstdint>

// Problem constants
#define BATCH   16384
#define MAXF    32
#define NFEAT   768
#define FT_OUT  1024
#define FULL_MASK 0xFFFFFFFFu

// fp16 copy of ft_w, rebuilt every kernel_launch (deterministic).
__device__ __half g_ftw_h[NFEAT * FT_OUT];

// ---------------------------------------------------------------------------
// Kernel 1: ft_w fp32 -> fp16 (one float4 per thread)
// ---------------------------------------------------------------------------
__global__ void convert_ftw_kernel(const float* __restrict__ ftw) {
    int i = blockIdx.x * blockDim.x + threadIdx.x;
    float4 v = reinterpret_cast<const float4*>(ftw)[i];
    __half2* dst = reinterpret_cast<__half2*>(g_ftw_h);
    dst[2 * i + 0] = __floats2half2_rn(v.x, v.y);
    dst[2 * i + 1] = __floats2half2_rn(v.z, v.w);
}

// ---------------------------------------------------------------------------
// Kernel 2: ONE warp per sample, full 1024 columns per warp.
// 8 samples per 256-thread CTA -> 32 samples in flight per SM (2x R9):
// maximizes cross-sample row collisions -> higher L1 hit rate.
// Per feature: 8x LDG.128 (side-at-a-time, MLP=4) + 32 HFMA2 + 0.5 LDS.128.
// Epilogue fully warp-local (no smem combine).
// ---------------------------------------------------------------------------
__global__ void __launch_bounds__(256, 4)
nnue_main_kernel(const float* __restrict__ values,
                 const int*   __restrict__ stm_idx,
                 const int*   __restrict__ nstm_idx,
                 const float* __restrict__ ft_b,
                 const float* __restrict__ out_w,
                 const float* __restrict__ out_b,
                 float*       __restrict__ out)
{
    __shared__ uint2 s_meta[8][MAXF];   // [sampleInCta][feature] = {idxS|idxN<<16, valbits}

    const int tid       = threadIdx.x;
    const int warpInCta = tid >> 5;
    const int lane      = tid & 31;
    const int b         = blockIdx.x * 8 + warpInCta;

    // Stage metadata: all 256 threads, one (sample, feature) each
    {
        const int s = tid >> 5;
        const int f = tid & 31;
        const int bg = blockIdx.x * 8 + s;
        const int is = stm_idx [bg * MAXF + f];
        const int in = nstm_idx[bg * MAXF + f];
        const float v = values [bg * MAXF + f];
        s_meta[s][f] = make_uint2((unsigned)is | ((unsigned)in << 16),
                                  __float_as_uint(v));
    }
    __syncthreads();

    // Lane's base: 16 B chunk at lane*16 within each 512 B quarter of a row.
    const char* W = reinterpret_cast<const char*>(g_ftw_h) + lane * 16;
    const uint4* meta4 = reinterpret_cast<const uint4*>(s_meta[warpInCta]);

    // Accumulators: 16 half2 per side (1024 cols / 32 lanes / 2 per half2)
    __half2 accS[16], accN[16];
    #pragma unroll
    for (int i = 0; i < 16; ++i) {
        accS[i] = __half2half2(__float2half_rn(0.0f));
        accN[i] = accS[i];
    }

    #pragma unroll 2
    for (int c = 0; c < 16; ++c) {          // 2 features per iteration
        const uint4 m = meta4[c];           // uniform LDS.128 broadcast

        #pragma unroll
        for (int ff = 0; ff < 2; ++ff) {
            const unsigned mi = ff ? m.z : m.x;
            const __half2 v2 = __float2half2_rn(__uint_as_float(ff ? m.w : m.y));
            const char* rS = W + (size_t)(mi & 0xFFFFu) * (FT_OUT * 2);
            const char* rN = W + (size_t)(mi >> 16)     * (FT_OUT * 2);

            // stm side: 4 independent LDG.128, then 16 HFMA2
            uint4 d0 = *reinterpret_cast<const uint4*>(rS);
            uint4 d1 = *reinterpret_cast<const uint4*>(rS + 512);
            uint4 d2 = *reinterpret_cast<const uint4*>(rS + 1024);
            uint4 d3 = *reinterpret_cast<const uint4*>(rS + 1536);
            accS[ 0] = __hfma2(v2, *reinterpret_cast<__half2*>(&d0.x), accS[ 0]);
            accS[ 1] = __hfma2(v2, *reinterpret_cast<__half2*>(&d0.y), accS[ 1]);
            accS[ 2] = __hfma2(v2, *reinterpret_cast<__half2*>(&d0.z), accS[ 2]);
            accS[ 3] = __hfma2(v2, *reinterpret_cast<__half2*>(&d0.w), accS[ 3]);
            accS[ 4] = __hfma2(v2, *reinterpret_cast<__half2*>(&d1.x), accS[ 4]);
            accS[ 5] = __hfma2(v2, *reinterpret_cast<__half2*>(&d1.y), accS[ 5]);
            accS[ 6] = __hfma2(v2, *reinterpret_cast<__half2*>(&d1.z), accS[ 6]);
            accS[ 7] = __hfma2(v2, *reinterpret_cast<__half2*>(&d1.w), accS[ 7]);
            accS[ 8] = __hfma2(v2, *reinterpret_cast<__half2*>(&d2.x), accS[ 8]);
            accS[ 9] = __hfma2(v2, *reinterpret_cast<__half2*>(&d2.y), accS[ 9]);
            accS[10] = __hfma2(v2, *reinterpret_cast<__half2*>(&d2.z), accS[10]);
            accS[11] = __hfma2(v2, *reinterpret_cast<__half2*>(&d2.w), accS[11]);
            accS[12] = __hfma2(v2, *reinterpret_cast<__half2*>(&d3.x), accS[12]);
            accS[13] = __hfma2(v2, *reinterpret_cast<__half2*>(&d3.y), accS[13]);
            accS[14] = __hfma2(v2, *reinterpret_cast<__half2*>(&d3.z), accS[14]);
            accS[15] = __hfma2(v2, *reinterpret_cast<__half2*>(&d3.w), accS[15]);

            // nstm side
            d0 = *reinterpret_cast<const uint4*>(rN);
            d1 = *reinterpret_cast<const uint4*>(rN + 512);
            d2 = *reinterpret_cast<const uint4*>(rN + 1024);
            d3 = *reinterpret_cast<const uint4*>(rN + 1536);
            accN[ 0] = __hfma2(v2, *reinterpret_cast<__half2*>(&d0.x), accN[ 0]);
            accN[ 1] = __hfma2(v2, *reinterpret_cast<__half2*>(&d0.y), accN[ 1]);
            accN[ 2] = __hfma2(v2, *reinterpret_cast<__half2*>(&d0.z), accN[ 2]);
            accN[ 3] = __hfma2(v2, *reinterpret_cast<__half2*>(&d0.w), accN[ 3]);
            accN[ 4] = __hfma2(v2, *reinterpret_cast<__half2*>(&d1.x), accN[ 4]);
            accN[ 5] = __hfma2(v2, *reinterpret_cast<__half2*>(&d1.y), accN[ 5]);
            accN[ 6] = __hfma2(v2, *reinterpret_cast<__half2*>(&d1.z), accN[ 6]);
            accN[ 7] = __hfma2(v2, *reinterpret_cast<__half2*>(&d1.w), accN[ 7]);
            accN[ 8] = __hfma2(v2, *reinterpret_cast<__half2*>(&d2.x), accN[ 8]);
            accN[ 9] = __hfma2(v2, *reinterpret_cast<__half2*>(&d2.y), accN[ 9]);
            accN[10] = __hfma2(v2, *reinterpret_cast<__half2*>(&d2.z), accN[10]);
            accN[11] = __hfma2(v2, *reinterpret_cast<__half2*>(&d2.w), accN[11]);
            accN[12] = __hfma2(v2, *reinterpret_cast<__half2*>(&d3.x), accN[12]);
            accN[13] = __hfma2(v2, *reinterpret_cast<__half2*>(&d3.y), accN[13]);
            accN[14] = __hfma2(v2, *reinterpret_cast<__half2*>(&d3.z), accN[14]);
            accN[15] = __hfma2(v2, *reinterpret_cast<__half2*>(&d3.w), accN[15]);
        }
    }

    // ----- epilogue: fp32 bias add, clip [0,1], dot with out_w -----
    // Lane's cols per quarter c: c*256 + lane*8 + 0..7 -> float4 idx c*64+lane*2+{0,1}
    const float4* fb4 = reinterpret_cast<const float4*>(ft_b);
    const float4* ow4 = reinterpret_cast<const float4*>(out_w);

    float partial = 0.0f;
    #pragma unroll
    for (int c = 0; c < 4; ++c) {
        const int fidx = c * 64 + lane * 2;
        float4 b0 = fb4[fidx + 0];
        float4 b1 = fb4[fidx + 1];
        #pragma unroll
        for (int side = 0; side < 2; ++side) {
            const __half2* acc = (side == 0) ? &accS[c*4] : &accN[c*4];
            const int owb = side * 256 + fidx;
            float4 w0 = ow4[owb + 0];
            float4 w1 = ow4[owb + 1];
            float2 p0 = __half22float2(acc[0]);
            float2 p1 = __half22float2(acc[1]);
            float2 p2 = __half22float2(acc[2]);
            float2 p3 = __half22float2(acc[3]);
            float hh;
            hh = fminf(fmaxf(p0.x + b0.x, 0.f), 1.f); partial = fmaf(hh, w0.x, partial);
            hh = fminf(fmaxf(p0.y + b0.y, 0.f), 1.f); partial = fmaf(hh, w0.y, partial);
            hh = fminf(fmaxf(p1.x + b0.z, 0.f), 1.f); partial = fmaf(hh, w0.z, partial);
            hh = fminf(fmaxf(p1.y + b0.w, 0.f), 1.f); partial = fmaf(hh, w0.w, partial);
            hh = fminf(fmaxf(p2.x + b1.x, 0.f), 1.f); partial = fmaf(hh, w1.x, partial);
            hh = fminf(fmaxf(p2.y + b1.y, 0.f), 1.f); partial = fmaf(hh, w1.y, partial);
            hh = fminf(fmaxf(p3.x + b1.z, 0.f), 1.f); partial = fmaf(hh, w1.z, partial);
            hh = fminf(fmaxf(p3.y + b1.w, 0.f), 1.f); partial = fmaf(hh, w1.w, partial);
        }
    }

    // warp reduce + finalize (warp-local, no smem)
    #pragma unroll
    for (int off = 16; off > 0; off >>= 1)
        partial += __shfl_xor_sync(FULL_MASK, partial, off);

    if (lane == 0) {
        float x = partial + out_b[0];
        out[b] = 1.0f / (1.0f + __expf(-x));
    }
}

// ---------------------------------------------------------------------------
// kernel_launch
// Inputs: values, stm_indices, nstm_indices, ft_w, ft_b, out_w, out_b
// ---------------------------------------------------------------------------
extern "C" void kernel_launch(void* const* d_in, const int* in_sizes, int n_in,
                              void* d_out, int out_size)
{
    const float* values   = (const float*)d_in[0];
    const int*   stm_idx  = (const int*)  d_in[1];
    const int*   nstm_idx = (const int*)  d_in[2];
    const float* ft_w     = (const float*)d_in[3];
    const float* ft_b     = (const float*)d_in[4];
    const float* out_w    = (const float*)d_in[5];
    const float* out_b    = (const float*)d_in[6];
    float*       out      = (float*)d_out;

    static bool attr_set = false;
    if (!attr_set) {
        // smem use is tiny; ask for the maximum L1 carveout.
        cudaFuncSetAttribute(nnue_main_kernel,
                             cudaFuncAttributePreferredSharedMemoryCarveout,
                             cudaSharedmemCarveoutMaxL1);
        attr_set = true;
    }

    convert_ftw_kernel<<<(NFEAT * FT_OUT / 4) / 256, 256>>>(ft_w);
    // one warp per sample, 8 samples per CTA -> 2048 CTAs
    nnue_main_kernel<<<BATCH / 8, 256>>>(values, stm_idx, nstm_idx,
                                         ft_b, out_w, out_b, out);
}

// round 11
// speedup vs baseline: 1.1901x; 1.1901x over previous
#include <cuda_runtime.h>
#include <cuda_fp16.h>
#include <cstdint>

// Problem constants
#define BATCH   16384
#define MAXF    32
#define NFEAT   768
#define FT_OUT  1024
#define FULL_MASK 0xFFFFFFFFu

// fp16 copy of ft_w, rebuilt every kernel_launch (deterministic).
__device__ __half g_ftw_h[NFEAT * FT_OUT];

// ---------------------------------------------------------------------------
// Kernel 1: ft_w fp32 -> fp16 (one float4 per thread)
// ---------------------------------------------------------------------------
__global__ void convert_ftw_kernel(const float* __restrict__ ftw) {
    int i = blockIdx.x * blockDim.x + threadIdx.x;
    float4 v = reinterpret_cast<const float4*>(ftw)[i];
    __half2* dst = reinterpret_cast<__half2*>(g_ftw_h);
    dst[2 * i + 0] = __floats2half2_rn(v.x, v.y);
    dst[2 * i + 1] = __floats2half2_rn(v.z, v.w);
}

// ---------------------------------------------------------------------------
// Kernel 2: TWO warps per sample (512 cols each), 4 samples per CTA.
// LDS.128 meta broadcast (2 features per read). Inner iteration processes
// 2 features side-at-a-time: 4 LDG.128 in flight, buffer = 16 regs ->
// total ~48 regs -> 5 CTAs/SM (40 warps) for better bubble coverage.
// ---------------------------------------------------------------------------
__global__ void __launch_bounds__(256, 5)
nnue_main_kernel(const float* __restrict__ values,
                 const int*   __restrict__ stm_idx,
                 const int*   __restrict__ nstm_idx,
                 const float* __restrict__ ft_b,
                 const float* __restrict__ out_w,
                 const float* __restrict__ out_b,
                 float*       __restrict__ out)
{
    __shared__ uint2 s_meta[4][MAXF];   // [sampleInCta][feature] = {idxS|idxN<<16, valbits}
    __shared__ float s_partial[8];

    const int tid       = threadIdx.x;
    const int warpInCta = tid >> 5;
    const int lane      = tid & 31;
    const int sInCta    = warpInCta >> 1;     // 4 samples per CTA
    const int h         = warpInCta & 1;      // column half: 0 or 1
    const int b         = blockIdx.x * 4 + sInCta;

    // Stage metadata: threads 0..127, one (sample, feature) each
    if (tid < 128) {
        const int s = tid >> 5;
        const int f = tid & 31;
        const int bg = blockIdx.x * 4 + s;
        const int is = stm_idx [bg * MAXF + f];
        const int in = nstm_idx[bg * MAXF + f];
        const float v = values [bg * MAXF + f];
        s_meta[s][f] = make_uint2((unsigned)is | ((unsigned)in << 16),
                                  __float_as_uint(v));
    }
    __syncthreads();

    // Warp owns cols [h*512, h*512+512). Lane chunks: +lane*16 B and +512 B.
    const char* Wq = reinterpret_cast<const char*>(g_ftw_h) + h * 1024 + lane * 16;
    const uint4* meta4 = reinterpret_cast<const uint4*>(s_meta[sInCta]);  // 2 feats/read

    __half2 accS[8], accN[8];
    #pragma unroll
    for (int i = 0; i < 8; ++i) {
        accS[i] = __half2half2(__float2half_rn(0.0f));
        accN[i] = accS[i];
    }

    #pragma unroll 4
    for (int c = 0; c < 16; ++c) {              // 2 features per iteration
        const uint4 m = meta4[c];               // uniform LDS.128 broadcast
        const __half2 v0 = __float2half2_rn(__uint_as_float(m.y));
        const __half2 v1 = __float2half2_rn(__uint_as_float(m.w));

        const char* rS0 = Wq + (size_t)(m.x & 0xFFFFu) * (FT_OUT * 2);
        const char* rS1 = Wq + (size_t)(m.z & 0xFFFFu) * (FT_OUT * 2);
        const char* rN0 = Wq + (size_t)(m.x >> 16)     * (FT_OUT * 2);
        const char* rN1 = Wq + (size_t)(m.z >> 16)     * (FT_OUT * 2);

        // ---- stm side: 4 independent LDG.128, then 16 HFMA2 ----
        {
            uint4 a0 = *reinterpret_cast<const uint4*>(rS0);
            uint4 a1 = *reinterpret_cast<const uint4*>(rS0 + 512);
            uint4 b0 = *reinterpret_cast<const uint4*>(rS1);
            uint4 b1 = *reinterpret_cast<const uint4*>(rS1 + 512);
            accS[0] = __hfma2(v0, *reinterpret_cast<__half2*>(&a0.x), accS[0]);
            accS[1] = __hfma2(v0, *reinterpret_cast<__half2*>(&a0.y), accS[1]);
            accS[2] = __hfma2(v0, *reinterpret_cast<__half2*>(&a0.z), accS[2]);
            accS[3] = __hfma2(v0, *reinterpret_cast<__half2*>(&a0.w), accS[3]);
            accS[4] = __hfma2(v0, *reinterpret_cast<__half2*>(&a1.x), accS[4]);
            accS[5] = __hfma2(v0, *reinterpret_cast<__half2*>(&a1.y), accS[5]);
            accS[6] = __hfma2(v0, *reinterpret_cast<__half2*>(&a1.z), accS[6]);
            accS[7] = __hfma2(v0, *reinterpret_cast<__half2*>(&a1.w), accS[7]);
            accS[0] = __hfma2(v1, *reinterpret_cast<__half2*>(&b0.x), accS[0]);
            accS[1] = __hfma2(v1, *reinterpret_cast<__half2*>(&b0.y), accS[1]);
            accS[2] = __hfma2(v1, *reinterpret_cast<__half2*>(&b0.z), accS[2]);
            accS[3] = __hfma2(v1, *reinterpret_cast<__half2*>(&b0.w), accS[3]);
            accS[4] = __hfma2(v1, *reinterpret_cast<__half2*>(&b1.x), accS[4]);
            accS[5] = __hfma2(v1, *reinterpret_cast<__half2*>(&b1.y), accS[5]);
            accS[6] = __hfma2(v1, *reinterpret_cast<__half2*>(&b1.z), accS[6]);
            accS[7] = __hfma2(v1, *reinterpret_cast<__half2*>(&b1.w), accS[7]);
        }
        // ---- nstm side ----
        {
            uint4 a0 = *reinterpret_cast<const uint4*>(rN0);
            uint4 a1 = *reinterpret_cast<const uint4*>(rN0 + 512);
            uint4 b0 = *reinterpret_cast<const uint4*>(rN1);
            uint4 b1 = *reinterpret_cast<const uint4*>(rN1 + 512);
            accN[0] = __hfma2(v0, *reinterpret_cast<__half2*>(&a0.x), accN[0]);
            accN[1] = __hfma2(v0, *reinterpret_cast<__half2*>(&a0.y), accN[1]);
            accN[2] = __hfma2(v0, *reinterpret_cast<__half2*>(&a0.z), accN[2]);
            accN[3] = __hfma2(v0, *reinterpret_cast<__half2*>(&a0.w), accN[3]);
            accN[4] = __hfma2(v0, *reinterpret_cast<__half2*>(&a1.x), accN[4]);
            accN[5] = __hfma2(v0, *reinterpret_cast<__half2*>(&a1.y), accN[5]);
            accN[6] = __hfma2(v0, *reinterpret_cast<__half2*>(&a1.z), accN[6]);
            accN[7] = __hfma2(v0, *reinterpret_cast<__half2*>(&a1.w), accN[7]);
            accN[0] = __hfma2(v1, *reinterpret_cast<__half2*>(&b0.x), accN[0]);
            accN[1] = __hfma2(v1, *reinterpret_cast<__half2*>(&b0.y), accN[1]);
            accN[2] = __hfma2(v1, *reinterpret_cast<__half2*>(&b0.z), accN[2]);
            accN[3] = __hfma2(v1, *reinterpret_cast<__half2*>(&b0.w), accN[3]);
            accN[4] = __hfma2(v1, *reinterpret_cast<__half2*>(&b1.x), accN[4]);
            accN[5] = __hfma2(v1, *reinterpret_cast<__half2*>(&b1.y), accN[5]);
            accN[6] = __hfma2(v1, *reinterpret_cast<__half2*>(&b1.z), accN[6]);
            accN[7] = __hfma2(v1, *reinterpret_cast<__half2*>(&b1.w), accN[7]);
        }
    }

    // ----- epilogue: fp32 bias add, clip [0,1], dot with out_w -----
    // Lane cols: u in {0,1}: col0 = h*512 + u*256 + lane*8
    //   -> float4 index fidx = h*128 + u*64 + lane*2 + {0,1}
    const float4* fb4 = reinterpret_cast<const float4*>(ft_b);
    const float4* ow4 = reinterpret_cast<const float4*>(out_w);

    float partial = 0.0f;
    #pragma unroll
    for (int u = 0; u < 2; ++u) {
        const int fidx = h * 128 + u * 64 + lane * 2;
        float4 b0 = fb4[fidx + 0];
        float4 b1 = fb4[fidx + 1];
        #pragma unroll
        for (int side = 0; side < 2; ++side) {
            const __half2* acc = (side == 0) ? &accS[u*4] : &accN[u*4];
            const int owb = side * 256 + fidx;
            float4 w0 = ow4[owb + 0];
            float4 w1 = ow4[owb + 1];
            float2 p0 = __half22float2(acc[0]);
            float2 p1 = __half22float2(acc[1]);
            float2 p2 = __half22float2(acc[2]);
            float2 p3 = __half22float2(acc[3]);
            float hh;
            hh = fminf(fmaxf(p0.x + b0.x, 0.f), 1.f); partial = fmaf(hh, w0.x, partial);
            hh = fminf(fmaxf(p0.y + b0.y, 0.f), 1.f); partial = fmaf(hh, w0.y, partial);
            hh = fminf(fmaxf(p1.x + b0.z, 0.f), 1.f); partial = fmaf(hh, w0.z, partial);
            hh = fminf(fmaxf(p1.y + b0.w, 0.f), 1.f); partial = fmaf(hh, w0.w, partial);
            hh = fminf(fmaxf(p2.x + b1.x, 0.f), 1.f); partial = fmaf(hh, w1.x, partial);
            hh = fminf(fmaxf(p2.y + b1.y, 0.f), 1.f); partial = fmaf(hh, w1.y, partial);
            hh = fminf(fmaxf(p3.x + b1.z, 0.f), 1.f); partial = fmaf(hh, w1.z, partial);
            hh = fminf(fmaxf(p3.y + b1.w, 0.f), 1.f); partial = fmaf(hh, w1.w, partial);
        }
    }

    // warp reduce
    #pragma unroll
    for (int off = 16; off > 0; off >>= 1)
        partial += __shfl_xor_sync(FULL_MASK, partial, off);

    if (lane == 0) s_partial[warpInCta] = partial;
    __syncthreads();

    // half-0 warp of each sample finalizes
    if (h == 0 && lane == 0) {
        float x = s_partial[warpInCta] + s_partial[warpInCta + 1] + out_b[0];
        out[b] = 1.0f / (1.0f + __expf(-x));
    }
}

// ---------------------------------------------------------------------------
// kernel_launch
// Inputs: values, stm_indices, nstm_indices, ft_w, ft_b, out_w, out_b
// ---------------------------------------------------------------------------
extern "C" void kernel_launch(void* const* d_in, const int* in_sizes, int n_in,
                              void* d_out, int out_size)
{
    const float* values   = (const float*)d_in[0];
    const int*   stm_idx  = (const int*)  d_in[1];
    const int*   nstm_idx = (const int*)  d_in[2];
    const float* ft_w     = (const float*)d_in[3];
    const float* ft_b     = (const float*)d_in[4];
    const float* out_w    = (const float*)d_in[5];
    const float* out_b    = (const float*)d_in[6];
    float*       out      = (float*)d_out;

    convert_ftw_kernel<<<(NFEAT * FT_OUT / 4) / 256, 256>>>(ft_w);
    // 4 samples per CTA -> 4096 CTAs
    nnue_main_kernel<<<BATCH / 4, 256>>>(values, stm_idx, nstm_idx,
                                         ft_b, out_w, out_b, out);
}